// round 3
// baseline (speedup 1.0000x reference)
#include <cuda_runtime.h>
#include <cuda_bf16.h>

// Problem constants
#define B_  16
#define C_  64
#define H_  192
#define W_  192

// Tiling: CTA = 64 wide x 32 tall spatial tile, 8 output channels.
// 256 threads as 16x16; each thread owns 4(w) x 2(h) pixels x 8 oc.
#define TW    64
#define TH    32
#define OCB   8
#define CIC   4
#define XPITCH 68   // smem pitch (floats) for 66-wide halo rows

typedef unsigned long long u64;

__device__ __forceinline__ u64 pack2(float lo, float hi) {
    u64 r;
    asm("mov.b64 %0, {%1, %2};" : "=l"(r) : "f"(lo), "f"(hi));
    return r;
}
__device__ __forceinline__ void unpack2(u64 v, float& lo, float& hi) {
    asm("mov.b64 {%0, %1}, %2;" : "=f"(lo), "=f"(hi) : "l"(v));
}
__device__ __forceinline__ void fma2(u64& acc, u64 a, u64 b) {
    asm("fma.rn.f32x2 %0, %1, %2, %0;" : "+l"(acc) : "l"(a), "l"(b));
}

__global__ __launch_bounds__(256, 2)
void conv_interp_kernel(const float* __restrict__ x,
                        const float* __restrict__ DoT,
                        const float* __restrict__ W0,
                        const float* __restrict__ W1,
                        float* __restrict__ y)
{
    __shared__ float s_x[CIC][34 * XPITCH];   // 4 * 34*68 * 4B = 36992 B
    __shared__ float s_w[CIC][9][OCB];        // 4 * 9 * 8 * 4B =  1152 B

    const int tile = blockIdx.x;              // 0..17 : 3 x-tiles, 6 y-tiles
    const int tx0  = (tile % (W_ / TW)) * TW;
    const int ty0  = (tile / (W_ / TW)) * TH;
    const int oc0  = blockIdx.y * OCB;
    const int b    = blockIdx.z;

    const int tid = threadIdx.x;
    const int lx  = tid & 15;
    const int ly  = tid >> 4;
    const int px  = lx * 4;                   // 0..60
    const int py  = ly * 2;                   // 0..30

    const float d  = DoT[b];
    const float od = 1.0f - d;

    // acc[oc][oy][pair] : pair0 = pixels (0,1), pair1 = pixels (2,3)
    u64 acc[OCB][2][2];
    #pragma unroll
    for (int oc = 0; oc < OCB; oc++)
        #pragma unroll
        for (int oy = 0; oy < 2; oy++) {
            acc[oc][oy][0] = 0ull;
            acc[oc][oy][1] = 0ull;
        }

    const float* xb = x + (size_t)b * C_ * H_ * W_;

    for (int ci0 = 0; ci0 < C_; ci0 += CIC) {
        __syncthreads();

        // ---- load x chunk with halo (34 rows x 66 cols per channel) ----
        for (int i = tid; i < CIC * 34 * 66; i += 256) {
            int ch  = i / (34 * 66);
            int rem = i - ch * (34 * 66);
            int r   = rem / 66;
            int c   = rem - r * 66;
            int gy  = ty0 - 1 + r;
            int gx  = tx0 - 1 + c;
            float v = 0.f;
            if ((unsigned)gy < H_ && (unsigned)gx < W_)
                v = xb[((size_t)(ci0 + ch) * H_ + gy) * W_ + gx];
            s_x[ch][r * XPITCH + c] = v;
        }

        // ---- interpolate weights into smem: [ci][tap][oc] ----
        // NOTE: 288 entries > 256 threads -> grid-stride loop (R2 bug fix).
        for (int i = tid; i < CIC * 9 * OCB; i += 256) {
            int ci  = i / (9 * OCB);
            int rem = i - ci * (9 * OCB);
            int tap = rem / OCB;
            int oc  = rem - tap * OCB;
            size_t g = ((size_t)(oc0 + oc) * C_ + (ci0 + ci)) * 9 + tap;
            s_w[ci][tap][oc] = od * W0[g] + d * W1[g];
        }

        __syncthreads();

        // ---- compute ----
        #pragma unroll
        for (int ci = 0; ci < CIC; ci++) {
            // 4 input rows x 6 input cols per thread
            float xs[4][6];
            #pragma unroll
            for (int r = 0; r < 4; r++) {
                const float* base = &s_x[ci][(py + r) * XPITCH + px];
                float4 v  = *(const float4*)base;
                float2 v2 = *(const float2*)(base + 4);
                xs[r][0] = v.x; xs[r][1] = v.y; xs[r][2] = v.z; xs[r][3] = v.w;
                xs[r][4] = v2.x; xs[r][5] = v2.y;
            }

            #pragma unroll
            for (int ky = 0; ky < 3; ky++) {
                #pragma unroll
                for (int kx = 0; kx < 3; kx++) {
                    const float4* wp = (const float4*)&s_w[ci][ky * 3 + kx][0];
                    float4 wa = wp[0], wb = wp[1];
                    u64 w2[OCB];
                    w2[0] = pack2(wa.x, wa.x); w2[1] = pack2(wa.y, wa.y);
                    w2[2] = pack2(wa.z, wa.z); w2[3] = pack2(wa.w, wa.w);
                    w2[4] = pack2(wb.x, wb.x); w2[5] = pack2(wb.y, wb.y);
                    w2[6] = pack2(wb.z, wb.z); w2[7] = pack2(wb.w, wb.w);

                    #pragma unroll
                    for (int oy = 0; oy < 2; oy++) {
                        const int r = oy + ky;
                        u64 xA = pack2(xs[r][kx],     xs[r][kx + 1]);
                        u64 xB = pack2(xs[r][kx + 2], xs[r][kx + 3]);
                        #pragma unroll
                        for (int oc = 0; oc < OCB; oc++) {
                            fma2(acc[oc][oy][0], w2[oc], xA);
                            fma2(acc[oc][oy][1], w2[oc], xB);
                        }
                    }
                }
            }
        }
    }

    // ---- store: 8 oc x 2 rows x float4 ----
    float* yb = y + (size_t)b * C_ * H_ * W_;
    #pragma unroll
    for (int oc = 0; oc < OCB; oc++) {
        #pragma unroll
        for (int oy = 0; oy < 2; oy++) {
            float4 o;
            unpack2(acc[oc][oy][0], o.x, o.y);
            unpack2(acc[oc][oy][1], o.z, o.w);
            float* p = yb + ((size_t)(oc0 + oc) * H_ + (ty0 + py + oy)) * W_ + (tx0 + px);
            *(float4*)p = o;
        }
    }
}

extern "C" void kernel_launch(void* const* d_in, const int* in_sizes, int n_in,
                              void* d_out, int out_size)
{
    const float* x   = (const float*)d_in[0];
    const float* DoT = (const float*)d_in[1];
    const float* W0  = (const float*)d_in[2];
    const float* W1  = (const float*)d_in[3];
    float* y = (float*)d_out;

    dim3 grid((W_ / TW) * (H_ / TH), C_ / OCB, B_);
    dim3 block(256);
    conv_interp_kernel<<<grid, block>>>(x, DoT, W0, W1, y);
}

// round 5
// speedup vs baseline: 4.2878x; 4.2878x over previous
#include <cuda_runtime.h>
#include <cuda_bf16.h>
#include <cstdint>

// ---------------- problem constants ----------------
#define B_   16
#define C_   64
#define H_   192
#define W_   192
#define NPIX (H_ * W_)

// ---------------- tiling ----------------
#define TR 8                 // tile rows
#define TC 32                // tile cols  (256 px per CTA, 64 oc)
#define HR 10                // halo rows
#define HC 34                // halo cols

// smem x layout per image: [slot = kf*4+p (16)][row (10)][col (34)][pair (2 words)]
// pair = (ci2 = kf*8 + p, ci2 = kf*8 + p + 4)  -> one LDS.64 yields mma b0,b1
#define ROWB  272            // 34 * 8 bytes per row
#define SLOTB (HR * ROWB)    // 2720 bytes
#define IMGB  (16 * SLOTB)   // 43520 bytes per image
#define SMEM_BYTES (2 * IMGB) // 87040 (hi image, then lo image)

// Pre-packed W fragments: [b][tap][kf][hl][mf][lane] uint4 (mma A-frag order)
__device__ uint4 g_wfrag[B_ * 9 * 4 * 2 * 4 * 32];

// ---------------- helpers ----------------
__device__ __forceinline__ uint32_t smem_u32(const void* p) {
    uint32_t a;
    asm("{ .reg .u64 t; cvta.to.shared.u64 t, %1; cvt.u32.u64 %0, t; }" : "=r"(a) : "l"(p));
    return a;
}
// packed bf16x2: low half = lo, high half = hi
__device__ __forceinline__ uint32_t cvt2(float lo, float hi) {
    uint32_t r;
    asm("cvt.rn.satfinite.bf16x2.f32 %0, %1, %2;" : "=r"(r) : "f"(hi), "f"(lo));
    return r;
}
__device__ __forceinline__ void split2(float v0, float v1, uint32_t& h2, uint32_t& l2) {
    h2 = cvt2(v0, v1);
    float h0 = __uint_as_float(h2 << 16);
    float h1 = __uint_as_float(h2 & 0xFFFF0000u);
    l2 = cvt2(v0 - h0, v1 - h1);
}
__device__ __forceinline__ void mma16816(float* c, const uint4& a, uint32_t b0, uint32_t b1) {
    asm volatile(
        "mma.sync.aligned.m16n8k16.row.col.f32.bf16.bf16.f32 "
        "{%0,%1,%2,%3}, {%4,%5,%6,%7}, {%8,%9}, {%0,%1,%2,%3};"
        : "+f"(c[0]), "+f"(c[1]), "+f"(c[2]), "+f"(c[3])
        : "r"(a.x), "r"(a.y), "r"(a.z), "r"(a.w), "r"(b0), "r"(b1));
}

// ---------------- prep: interpolate + split + pack W fragments ----------------
// grid (9, 16) x 512 threads: thread = (kf, mf, lane)
__global__ void prep_w(const float* __restrict__ W0, const float* __restrict__ W1,
                       const float* __restrict__ DoT)
{
    const int tap = blockIdx.x;
    const int b   = blockIdx.y;
    const float d = DoT[b], od = 1.0f - d;

    const int t    = threadIdx.x;
    const int kf   = t >> 7;
    const int mf   = (t >> 5) & 3;
    const int lane = t & 31;
    const int m    = mf * 16 + (lane >> 2);
    const int k    = kf * 16 + (lane & 3) * 2;

    // mma A-frag reg order: r0=(m,k..k+1) r1=(m+8,k..) r2=(m,k+8..) r3=(m+8,k+8..)
    float v[4][2];
    #pragma unroll
    for (int r = 0; r < 4; r++) {
        const int oc = m + (r & 1) * 8;
        const int ci = k + (r >> 1) * 8;
        const size_t g0 = (size_t)(oc * C_ + ci) * 9 + tap;
        const size_t g1 = g0 + 9;
        v[r][0] = od * W0[g0] + d * W1[g0];
        v[r][1] = od * W0[g1] + d * W1[g1];
    }
    uint4 hi, lo;
    uint32_t* hp = &hi.x;
    uint32_t* lp = &lo.x;
    #pragma unroll
    for (int r = 0; r < 4; r++) split2(v[r][0], v[r][1], hp[r], lp[r]);

    const size_t base = ((((size_t)(b * 9 + tap) * 4 + kf) * 2) * 4 + mf) * 32 + lane;
    g_wfrag[base]       = hi;   // hl = 0
    g_wfrag[base + 128] = lo;   // hl = 1  (stride 4*32 uint4)
}

// ---------------- main kernel ----------------
__global__ __launch_bounds__(256, 2)
void conv_mma(const float* __restrict__ x, float* __restrict__ y)
{
    extern __shared__ char smem[];
    const uint32_t sx = smem_u32(smem);

    const int tid  = threadIdx.x;
    const int wid  = tid >> 5;          // warp = tile row (0..7)
    const int lane = tid & 31;
    const int p_   = lane & 3;
    const int q    = lane >> 2;
    const int b    = blockIdx.y;
    const int py0  = (blockIdx.x / 6) * TR;
    const int px0  = (blockIdx.x % 6) * TC;

    const float* xb = x + (size_t)b * C_ * NPIX;

    // ---- fill smem: fp32 halo -> bf16 hi/lo split, fragment-friendly layout ----
    for (int idx = tid; idx < 32 * HR * HC; idx += 256) {
        const int ci2 = idx / (HR * HC);
        const int rem = idx - ci2 * (HR * HC);
        const int r   = rem / HC;
        const int c   = rem - r * HC;
        const int gy  = py0 - 1 + r;
        const int gx  = px0 - 1 + c;
        float v0 = 0.f, v1 = 0.f;
        if ((unsigned)gy < H_ && (unsigned)gx < W_) {
            const float* p = xb + (size_t)(2 * ci2) * NPIX + gy * W_ + gx;
            v0 = p[0];
            v1 = p[NPIX];
        }
        uint32_t h2, l2;
        split2(v0, v1, h2, l2);
        const int kfi = ci2 >> 3, l = ci2 & 7, pp = l & 3, e = l >> 2;
        const uint32_t off = (uint32_t)((kfi * 4 + pp) * SLOTB + r * ROWB + c * 8 + e * 4);
        asm volatile("st.shared.b32 [%0], %1;" :: "r"(sx + off),        "r"(h2) : "memory");
        asm volatile("st.shared.b32 [%0], %1;" :: "r"(sx + IMGB + off), "r"(l2) : "memory");
    }
    __syncthreads();

    float acc[4][4][4];
    #pragma unroll
    for (int mf = 0; mf < 4; mf++)
        #pragma unroll
        for (int cs = 0; cs < 4; cs++) {
            acc[mf][cs][0] = 0.f; acc[mf][cs][1] = 0.f;
            acc[mf][cs][2] = 0.f; acc[mf][cs][3] = 0.f;
        }

    const uint4* wf = g_wfrag + (size_t)(b * 9) * (4 * 2 * 4 * 32);
    const uint32_t thr_base = sx + (uint32_t)(p_ * SLOTB + q * 8);

    for (int tap = 0; tap < 9; tap++) {
        const int ky = tap / 3;
        const int kx = tap - ky * 3;
        const uint32_t tap_off = (uint32_t)((wid + ky) * ROWB + kx * 8);
        const uint4* wft = wf + tap * (4 * 2 * 4 * 32);

        #pragma unroll
        for (int kf = 0; kf < 4; kf++) {
            const uint4* wfk = wft + kf * (2 * 4 * 32);
            uint4 ah[4], al[4];
            #pragma unroll
            for (int mf = 0; mf < 4; mf++) {
                ah[mf] = wfk[mf * 32 + lane];
                al[mf] = wfk[128 + mf * 32 + lane];
            }
            const uint32_t a_base = thr_base + tap_off + (uint32_t)(kf * 4 * SLOTB);

            #pragma unroll
            for (int cs = 0; cs < 4; cs++) {
                const uint32_t addr = a_base + cs * 64;
                uint32_t bh0, bh1, bl0, bl1;
                asm volatile("ld.shared.v2.b32 {%0,%1}, [%2];"
                             : "=r"(bh0), "=r"(bh1) : "r"(addr));
                asm volatile("ld.shared.v2.b32 {%0,%1}, [%2];"
                             : "=r"(bl0), "=r"(bl1) : "r"(addr + IMGB));
                #pragma unroll
                for (int mf = 0; mf < 4; mf++) mma16816(acc[mf][cs], ah[mf], bh0, bh1);
                #pragma unroll
                for (int mf = 0; mf < 4; mf++) mma16816(acc[mf][cs], al[mf], bh0, bh1);
                #pragma unroll
                for (int mf = 0; mf < 4; mf++) mma16816(acc[mf][cs], ah[mf], bl0, bl1);
            }
        }
    }

    // ---- epilogue: D rows = oc, cols = pixels ----
    float* yb = y + (size_t)b * C_ * NPIX;
    const int gy = py0 + wid;
    #pragma unroll
    for (int mf = 0; mf < 4; mf++) {
        const int oc = mf * 16 + q;
        #pragma unroll
        for (int cs = 0; cs < 4; cs++) {
            const int gx = px0 + cs * 8 + p_ * 2;
            float2* o0 = (float2*)(yb + (size_t)oc * NPIX + gy * W_ + gx);
            *o0 = make_float2(acc[mf][cs][0], acc[mf][cs][1]);
            float2* o1 = (float2*)(yb + (size_t)(oc + 8) * NPIX + gy * W_ + gx);
            *o1 = make_float2(acc[mf][cs][2], acc[mf][cs][3]);
        }
    }
}

// ---------------- launch ----------------
extern "C" void kernel_launch(void* const* d_in, const int* in_sizes, int n_in,
                              void* d_out, int out_size)
{
    const float* x   = (const float*)d_in[0];
    const float* DoT = (const float*)d_in[1];
    const float* W0  = (const float*)d_in[2];
    const float* W1  = (const float*)d_in[3];
    float* y = (float*)d_out;

    cudaFuncSetAttribute(conv_mma, cudaFuncAttributeMaxDynamicSharedMemorySize, SMEM_BYTES);

    prep_w<<<dim3(9, B_), 512>>>(W0, W1, DoT);
    conv_mma<<<dim3((H_ / TR) * (W_ / TC), B_), 256, SMEM_BYTES>>>(x, y);
}